// round 8
// baseline (speedup 1.0000x reference)
#include <cuda_runtime.h>
#include <cstdint>
#include <cstddef>

// ---------------- problem constants ----------------
#define BB 2
#define CC 256
#define HH 128
#define WW 128
#define HW 16384
#define MPIX 32768
#define NCLS 80
#define NMS_CAND 1000
#define MAX_DET 100
#define KB 32
#define STG (KB * 132)     // floats per stage per array
#define NPANEL (256 / KB)  // 8
#define STG16 (16 * 132)

#define TPL 1536                  // gemm tiles per layer (3 heads * 256 mb * 2 nb)
#define TOT_GEMM (5 * TPL)        // 7680
#define TOT_ALL (TOT_GEMM + 256)  // + outdec tiles

// ---------------- scratch ----------------
// activations kept TRANSPOSED: [256][MPIX], ping-pong by layer parity
__device__ float g_bA[3][(size_t)CC * MPIX];    // parity 0 (layers 0,2,4)
__device__ float g_bB[3][(size_t)CC * MPIX];    // parity 1 (layers 1,3)
__device__ float g_WT[15 * 256 * 256];          // pre-transposed weights [k][n]
__device__ int   g_ticket;
__device__ int   g_done[5 * 768];               // [layer][head][mb] completion counters
__device__ float g_score[MPIX];
__device__ int   g_label[MPIX];
__device__ float g_boxes[(size_t)MPIX * 4];
__device__ float g_cand_sc[BB * NMS_CAND];
__device__ int   g_cand_lab[BB * NMS_CAND];
__device__ float g_cand_box[BB * NMS_CAND * 4];
__device__ unsigned g_mask[(size_t)BB * NMS_CAND * 32];
__device__ unsigned g_keep[BB * 32];

// ---------------- helpers ----------------
__device__ __forceinline__ unsigned smem_addr(const void* p) {
    return (unsigned)__cvta_generic_to_shared(p);
}
__device__ __forceinline__ void cpasync16(unsigned dst, const float* src) {
    asm volatile("cp.async.cg.shared.global [%0], [%1], 16;\n" :: "r"(dst), "l"(src));
}
__device__ __forceinline__ void cp_commit() {
    asm volatile("cp.async.commit_group;\n" ::: "memory");
}
template <int N>
__device__ __forceinline__ void cp_wait() {
    asm volatile("cp.async.wait_group %0;\n" :: "n"(N) : "memory");
}
__device__ __forceinline__ void ffma2(unsigned long long& d, unsigned long long a, unsigned long long b) {
    asm("fma.rn.f32x2 %0, %1, %2, %0;" : "+l"(d) : "l"(a), "l"(b));
}
__device__ __forceinline__ unsigned long long dup2(float x) {
    unsigned long long r;
    asm("mov.b64 %0, {%1, %1};" : "=l"(r) : "f"(x));
    return r;
}
__device__ __forceinline__ void unpack2(unsigned long long v, float& lo, float& hi) {
    asm("mov.b64 {%0, %1}, %2;" : "=f"(lo), "=f"(hi) : "l"(v));
}
__device__ __forceinline__ float sigmoidf_(float x) { return 1.f / (1.f + expf(-x)); }

// ---------------- reset (per-replay state) ----------------
__global__ void reset_k() {
    if (threadIdx.x == 0) g_ticket = 0;
    for (int j = threadIdx.x; j < 5 * 768; j += 256) g_done[j] = 0;
}

// ---------------- weight transpose: W[n][k] -> WT[k][n], 15 matrices ----------------
__global__ void wtrans_k(const float* __restrict__ cwin, const float* __restrict__ owin,
                         const float* __restrict__ bwin, const float* __restrict__ cwh,
                         const float* __restrict__ owh, const float* __restrict__ bwh) {
    __shared__ float t[32][33];
    int z = blockIdx.z;
    const float* src;
    if (z < 3) src = z == 0 ? cwin : (z == 1 ? owin : bwin);
    else {
        int h = (z - 3) >> 2, li = (z - 3) & 3;
        const float* hh = h == 0 ? cwh : (h == 1 ? owh : bwh);
        src = hh + (size_t)li * 65536;
    }
    float* dst = g_WT + (size_t)z * 65536;
    int x0 = blockIdx.x * 32, y0 = blockIdx.y * 32;
    int tx = threadIdx.x, ty = threadIdx.y;   // (32,8)
    #pragma unroll
    for (int i = 0; i < 32; i += 8)
        t[ty + i][tx] = src[(size_t)(y0 + ty + i) * 256 + x0 + tx];
    __syncthreads();
    #pragma unroll
    for (int i = 0; i < 32; i += 8)
        dst[(size_t)(x0 + ty + i) * 256 + y0 + tx] = t[tx][ty + i];
}

// ---------------- persistent chain: 5 GEMM layers + fused out/decode ----------------
__global__ void __launch_bounds__(256, 2) persist_k(
    const float* __restrict__ feat,
    const float* __restrict__ cbin, const float* __restrict__ obin, const float* __restrict__ bbin,
    const float* __restrict__ cbh, const float* __restrict__ obh, const float* __restrict__ bbh,
    const float* __restrict__ cw, const float* __restrict__ cb,
    const float* __restrict__ ow, const float* __restrict__ ob,
    const float* __restrict__ bw, const float* __restrict__ bbx)
{
    extern __shared__ __align__(16) float sm[];
    __shared__ int s_ticket;
    const int tid = threadIdx.x;
    const int tx = tid & 15, ty = tid >> 4;

    while (true) {
        if (tid == 0) s_ticket = atomicAdd(&g_ticket, 1);
        __syncthreads();
        const int t = s_ticket;
        if (t >= TOT_ALL) return;

        if (t < TOT_GEMM) {
            // ---- GEMM tile ----
            const int l = t / TPL, r = t % TPL;
            const int h = r >> 9, q = r & 511;
            const int mb = q >> 1, nb = q & 1;
            const int m0 = mb * 128, n0 = nb * 128;

            if (l > 0) {
                if (tid == 0) {
                    int* flag = &g_done[(l - 1) * 768 + h * 256 + mb];
                    while (atomicAdd(flag, 0) < 2) __nanosleep(64);
                }
                __syncthreads();
                __threadfence();
            }

            float* buf0 = &g_bA[h][0];
            float* buf1 = &g_bB[h][0];
            float* Cout = ((l & 1) ? buf1 : buf0);
            const float* Abase;
            const float* Asrc = nullptr;   // residual source ([n][m], stride MPIX)
            size_t Astride;
            if (l == 0) {
                int b = m0 >> 14;
                Abase = feat + (size_t)b * CC * HW + (m0 & (HW - 1));
                Astride = HW;
            } else {
                Asrc = ((l - 1) & 1) ? buf1 : buf0;
                Abase = Asrc + m0;
                Astride = MPIX;
            }
            const int z = (l == 0) ? h : (3 + h * 4 + (l - 1));
            const float* Wt = g_WT + (size_t)z * 65536;
            const float* bias = (l == 0)
                ? (h == 0 ? cbin : h == 1 ? obin : bbin)
                : ((h == 0 ? cbh : h == 1 ? obh : bbh) + (l - 1) * 256);

            float* As = sm;              // [3][KB][132]
            float* Bs = sm + 3 * STG;    // [3][KB][132]

            auto load_panel = [&](int p, int s) {
                float* Asd = As + s * STG;
                float* Bsd = Bs + s * STG;
                #pragma unroll
                for (int lq = 0; lq < 4; lq++) {
                    int idx = tid + lq * 256;
                    int k = idx >> 5, c4 = idx & 31;
                    cpasync16(smem_addr(&Asd[k * 132 + c4 * 4]),
                              Abase + (size_t)(p * KB + k) * Astride + c4 * 4);
                }
                #pragma unroll
                for (int lq = 0; lq < 4; lq++) {
                    int idx = tid + lq * 256;
                    int k = idx >> 5, c4 = idx & 31;
                    cpasync16(smem_addr(&Bsd[k * 132 + c4 * 4]),
                              Wt + (size_t)(p * KB + k) * 256 + n0 + c4 * 4);
                }
                cp_commit();
            };

            unsigned long long acc2[8][4];
            #pragma unroll
            for (int j = 0; j < 8; j++)
                #pragma unroll
                for (int qq = 0; qq < 4; qq++) acc2[j][qq] = 0ull;

            load_panel(0, 0);
            load_panel(1, 1);

            #pragma unroll 1
            for (int p = 0; p < NPANEL; p++) {
                if (p < NPANEL - 1) cp_wait<1>(); else cp_wait<0>();
                __syncthreads();
                if (p + 2 < NPANEL) load_panel(p + 2, (p + 2) % 3);
                const float* Asd = As + (p % 3) * STG;
                const float* Bsd = Bs + (p % 3) * STG;
                #pragma unroll 8
                for (int kk = 0; kk < KB; kk++) {
                    ulonglong2 aA = *(const ulonglong2*)&Asd[kk * 132 + 4 * ty];
                    ulonglong2 aB = *(const ulonglong2*)&Asd[kk * 132 + 64 + 4 * ty];
                    float4 bb0 = *(const float4*)&Bsd[kk * 132 + 4 * tx];
                    float4 bb1 = *(const float4*)&Bsd[kk * 132 + 64 + 4 * tx];
                    unsigned long long am[4] = {aA.x, aA.y, aB.x, aB.y};
                    unsigned long long bd[8] = {dup2(bb0.x), dup2(bb0.y), dup2(bb0.z), dup2(bb0.w),
                                                dup2(bb1.x), dup2(bb1.y), dup2(bb1.z), dup2(bb1.w)};
                    #pragma unroll
                    for (int j = 0; j < 8; j++)
                        #pragma unroll
                        for (int qq = 0; qq < 4; qq++)
                            ffma2(acc2[j][qq], am[qq], bd[j]);
                }
            }

            #pragma unroll
            for (int j = 0; j < 8; j++) {
                int n = n0 + ((j < 4) ? (4 * tx + j) : (64 + 4 * tx + (j - 4)));
                float bv = bias[n];
                float f0, f1, f2, f3, h0, h1, h2, h3;
                unpack2(acc2[j][0], f0, f1);
                unpack2(acc2[j][1], f2, f3);
                unpack2(acc2[j][2], h0, h1);
                unpack2(acc2[j][3], h2, h3);
                float4 v0 = make_float4(f0 + bv, f1 + bv, f2 + bv, f3 + bv);
                float4 v1 = make_float4(h0 + bv, h1 + bv, h2 + bv, h3 + bv);
                if (l > 0) {
                    float4 r0 = __ldcg((const float4*)(Asrc + (size_t)n * MPIX + m0 + 4 * ty));
                    float4 r1 = __ldcg((const float4*)(Asrc + (size_t)n * MPIX + m0 + 64 + 4 * ty));
                    v0.x += r0.x; v0.y += r0.y; v0.z += r0.z; v0.w += r0.w;
                    v1.x += r1.x; v1.y += r1.y; v1.z += r1.z; v1.w += r1.w;
                }
                *(float4*)(Cout + (size_t)n * MPIX + m0 + 4 * ty) = v0;
                *(float4*)(Cout + (size_t)n * MPIX + m0 + 64 + 4 * ty) = v1;
            }
            __threadfence();
            __syncthreads();
            if (tid == 0) atomicAdd(&g_done[l * 768 + h * 256 + mb], 1);
            __syncthreads();
        } else {
            // ---- fused out-layers + decode tile ----
            const int mb = t - TOT_GEMM;
            const int m0 = mb * 128;

            if (tid == 0) {
                #pragma unroll
                for (int h = 0; h < 3; h++) {
                    int* flag = &g_done[4 * 768 + h * 256 + mb];
                    while (atomicAdd(flag, 0) < 2) __nanosleep(64);
                }
            }
            __syncthreads();
            __threadfence();

            const float* Acls = &g_bA[0][0];   // layer-4 outputs live in parity-0
            const float* Aobj = &g_bA[1][0];
            const float* Abox = &g_bA[2][0];

            float* As_c = sm;
            float* As_b = sm + STG16;
            float* As_o = sm + 2 * STG16;
            float* Bsw  = sm + 3 * STG16;
            float* sbias = sm + 3 * STG16 + 1600;
            float* slog = sm + 3 * STG16 + 1712;

            if (tid < 96) {
                float bv = 0.f;
                if (tid < 80) bv = cb[tid];
                else if (tid < 84) bv = bbx[tid - 80];
                else if (tid == 84) bv = ob[0];
                sbias[tid] = bv;
            }

            float acc[8][6];
            #pragma unroll
            for (int i = 0; i < 8; i++)
                #pragma unroll
                for (int j = 0; j < 6; j++) acc[i][j] = 0.f;

            #pragma unroll 1
            for (int p = 0; p < 16; p++) {
                __syncthreads();
                #pragma unroll
                for (int lq = 0; lq < 2; lq++) {
                    int idx = tid + lq * 256;
                    int k = idx >> 5, c4 = idx & 31;
                    size_t off = (size_t)(p * 16 + k) * MPIX + m0 + c4 * 4;
                    *(float4*)&As_c[k * 132 + c4 * 4] = __ldcg((const float4*)(Acls + off));
                    *(float4*)&As_b[k * 132 + c4 * 4] = __ldcg((const float4*)(Abox + off));
                    *(float4*)&As_o[k * 132 + c4 * 4] = __ldcg((const float4*)(Aobj + off));
                }
                #pragma unroll
                for (int lq = 0; lq < 6; lq++) {
                    int idx = tid + lq * 256;
                    int k = idx & 15, slot = idx >> 4;
                    float v = 0.f;
                    if (slot < 80)       v = cw[slot * 256 + p * 16 + k];
                    else if (slot < 84)  v = bw[(slot - 80) * 256 + p * 16 + k];
                    else if (slot == 84) v = ow[p * 16 + k];
                    Bsw[k * 100 + slot] = v;
                }
                __syncthreads();

                const float* As_x = (tx < 4) ? As_b : (tx == 4 ? As_o : As_c);
                #pragma unroll
                for (int kk = 0; kk < 16; kk++) {
                    float4 a0 = *(const float4*)&As_c[kk * 132 + ty * 8];
                    float4 a1 = *(const float4*)&As_c[kk * 132 + ty * 8 + 4];
                    float4 x0 = *(const float4*)&As_x[kk * 132 + ty * 8];
                    float4 x1 = *(const float4*)&As_x[kk * 132 + ty * 8 + 4];
                    float ac[8] = {a0.x, a0.y, a0.z, a0.w, a1.x, a1.y, a1.z, a1.w};
                    float ax[8] = {x0.x, x0.y, x0.z, x0.w, x1.x, x1.y, x1.z, x1.w};
                    float b[6];
                    #pragma unroll
                    for (int j = 0; j < 6; j++) b[j] = Bsw[kk * 100 + tx + 16 * j];
                    #pragma unroll
                    for (int i = 0; i < 8; i++) {
                        #pragma unroll
                        for (int j = 0; j < 5; j++)
                            acc[i][j] = fmaf(ac[i], b[j], acc[i][j]);
                        acc[i][5] = fmaf(ax[i], b[5], acc[i][5]);
                    }
                }
            }

            __syncthreads();
            #pragma unroll
            for (int i = 0; i < 8; i++)
                #pragma unroll
                for (int j = 0; j < 6; j++) {
                    int col = tx + 16 * j;
                    slog[(ty * 8 + i) * 97 + col] = acc[i][j] + sbias[col];
                }
            __syncthreads();

            if (tid < 128) {
                const float* lg = &slog[tid * 97];
                float objp = sigmoidf_(lg[84]);
                float best = -1.f; int bl = 0;
                #pragma unroll 4
                for (int c = 0; c < NCLS; c++) {
                    float pr = sigmoidf_(lg[c]) * objp;
                    if (pr > best) { best = pr; bl = c; }
                }
                int n = m0 + tid;
                g_score[n] = best;
                g_label[n] = bl;
                int hw = n & (HW - 1);
                int h2 = hw >> 7, w2 = hw & 127;
                float px = (w2 + 0.5f) * 8.f;
                float py = (h2 + 0.5f) * 8.f;
                float lft = expf(lg[80]) * 8.f;
                float top = expf(lg[81]) * 8.f;
                float rgt = expf(lg[82]) * 8.f;
                float bot = expf(lg[83]) * 8.f;
                g_boxes[(size_t)n * 4 + 0] = px - lft;
                g_boxes[(size_t)n * 4 + 1] = py - top;
                g_boxes[(size_t)n * 4 + 2] = px + rgt;
                g_boxes[(size_t)n * 4 + 3] = py + bot;
            }
            __syncthreads();
        }
    }
}

// ---------------- exact top-1000: histogram select + compact + bitonic 4096 ----------------
__global__ void topk_k() {
    __shared__ int hist[256];
    __shared__ int s_b1, s_n1, s_thr, s_cnt;
    __shared__ unsigned long long skey[4096];
    int b = blockIdx.x;
    int tid = threadIdx.x;   // 1024

    if (tid < 256) hist[tid] = 0;
    __syncthreads();
    for (int i = tid; i < HW; i += 1024) {
        unsigned u = __float_as_uint(g_score[b * HW + i]);
        atomicAdd(&hist[u >> 24], 1);
    }
    __syncthreads();
    if (tid == 0) {
        int acc = 0; int bin = 255;
        for (; bin > 0; bin--) { if (acc + hist[bin] >= NMS_CAND) break; acc += hist[bin]; }
        s_b1 = bin; s_n1 = acc;
    }
    __syncthreads();
    int b1 = s_b1, n1 = s_n1;
    if (tid < 256) hist[tid] = 0;
    __syncthreads();
    for (int i = tid; i < HW; i += 1024) {
        unsigned u = __float_as_uint(g_score[b * HW + i]);
        if ((int)(u >> 24) == b1) atomicAdd(&hist[(u >> 16) & 255], 1);
    }
    __syncthreads();
    if (tid == 0) {
        int acc = n1; int bin = 255;
        for (; bin > 0; bin--) { if (acc + hist[bin] >= NMS_CAND) break; acc += hist[bin]; }
        s_thr = (b1 << 8) | bin;
        s_cnt = 0;
    }
    __syncthreads();
    unsigned thr = (unsigned)s_thr;
    for (int i = tid; i < HW; i += 1024) {
        unsigned u = __float_as_uint(g_score[b * HW + i]);
        if ((u >> 16) >= thr) {
            int pos = atomicAdd(&s_cnt, 1);
            if (pos < 4096)
                skey[pos] = ((unsigned long long)(~u) << 32) | (unsigned)i;
        }
    }
    __syncthreads();
    int cnt = s_cnt < 4096 ? s_cnt : 4096;
    for (int i = tid; i < 4096; i += 1024)
        if (i >= cnt) skey[i] = 0xFFFFFFFFFFFFFFFFull;
    __syncthreads();

    for (int k = 2; k <= 4096; k <<= 1) {
        for (int j = k >> 1; j > 0; j >>= 1) {
            #pragma unroll
            for (int l = 0; l < 4; l++) {
                int i = tid + l * 1024;
                int ixj = i ^ j;
                if (ixj > i) {
                    bool up = ((i & k) == 0);
                    unsigned long long a = skey[i], c = skey[ixj];
                    if (up ? (a > c) : (a < c)) { skey[i] = c; skey[ixj] = a; }
                }
            }
            __syncthreads();
        }
    }

    if (tid < NMS_CAND) {
        unsigned long long key = skey[tid];
        int idx = (int)(unsigned)key;
        float s = __uint_as_float(~(unsigned)(key >> 32));
        int g = b * HW + idx;
        int dst = b * NMS_CAND + tid;
        g_cand_sc[dst] = s;
        g_cand_lab[dst] = g_label[g];
        #pragma unroll
        for (int q = 0; q < 4; q++)
            g_cand_box[dst * 4 + q] = g_boxes[(size_t)g * 4 + q];
    }
}

// ---------------- NMS ----------------
__global__ void nms_mask_k() {
    int i = blockIdx.x;
    int b = blockIdx.y;
    int j = threadIdx.x;
    const float* bi = &g_cand_box[(b * NMS_CAND + i) * 4];
    float ix1 = bi[0], iy1 = bi[1], ix2 = bi[2], iy2 = bi[3];
    float ai = fmaxf(ix2 - ix1, 0.f) * fmaxf(iy2 - iy1, 0.f);
    bool pred = false;
    if (j < NMS_CAND && j > i) {
        const float* bj = &g_cand_box[(b * NMS_CAND + j) * 4];
        float aj = fmaxf(bj[2] - bj[0], 0.f) * fmaxf(bj[3] - bj[1], 0.f);
        float xx1 = fmaxf(ix1, bj[0]), yy1 = fmaxf(iy1, bj[1]);
        float xx2 = fminf(ix2, bj[2]), yy2 = fminf(iy2, bj[3]);
        float iw = fmaxf(xx2 - xx1, 0.f), ih = fmaxf(yy2 - yy1, 0.f);
        float inter = iw * ih;
        float iou = inter / (ai + aj - inter + 1e-6f);
        pred = iou > 0.65f;
    }
    unsigned m = __ballot_sync(0xffffffffu, pred);
    if ((j & 31) == 0)
        g_mask[((size_t)(b * NMS_CAND + i)) * 32 + (j >> 5)] = m;
}

__global__ void nms_reduce_k() {
    extern __shared__ unsigned smask[];
    int b = blockIdx.x;
    for (int t = threadIdx.x; t < NMS_CAND * 32; t += 1024)
        smask[t] = g_mask[(size_t)b * NMS_CAND * 32 + t];
    __syncthreads();
    if (threadIdx.x < 32) {
        int lane = threadIdx.x;
        unsigned removed = 0u;
        for (int i = 0; i < NMS_CAND; i++) {
            unsigned rw = __shfl_sync(0xffffffffu, removed, i >> 5);
            if (!((rw >> (i & 31)) & 1u))
                removed |= smask[i * 32 + lane];
        }
        g_keep[b * 32 + lane] = ~removed;
    }
}

// ---------------- final select ----------------
__global__ void select_k(float* __restrict__ out) {
    __shared__ int ps[1024];
    __shared__ int s_total;
    int b = blockIdx.x;
    int tid = threadIdx.x;
    int kept = 0;
    if (tid < NMS_CAND)
        kept = (g_keep[b * 32 + (tid >> 5)] >> (tid & 31)) & 1;
    ps[tid] = kept;
    __syncthreads();
    for (int off = 1; off < 1024; off <<= 1) {
        int v = (tid >= off) ? ps[tid - off] : 0;
        __syncthreads();
        ps[tid] += v;
        __syncthreads();
    }
    if (tid == 1023) s_total = ps[1023];
    __syncthreads();
    int total = s_total;
    if (tid < NMS_CAND) {
        int excl = ps[tid] - kept;
        int pos = kept ? excl : total + (tid - excl);
        if (pos < MAX_DET) {
            int src = b * NMS_CAND + tid;
            out[(b * MAX_DET + pos) * 4 + 0] = g_cand_box[src * 4 + 0];
            out[(b * MAX_DET + pos) * 4 + 1] = g_cand_box[src * 4 + 1];
            out[(b * MAX_DET + pos) * 4 + 2] = g_cand_box[src * 4 + 2];
            out[(b * MAX_DET + pos) * 4 + 3] = g_cand_box[src * 4 + 3];
            out[BB * MAX_DET * 4 + b * MAX_DET + pos] = kept ? g_cand_sc[src] : 0.f;
            out[BB * MAX_DET * 5 + b * MAX_DET + pos] = (float)g_cand_lab[src];
        }
    }
}

// ---------------- launch ----------------
extern "C" void kernel_launch(void* const* d_in, const int* in_sizes, int n_in,
                              void* d_out, int out_size) {
    (void)in_sizes; (void)n_in; (void)out_size;
    const float* feat = (const float*)d_in[0];
    const float* cls_w_in  = (const float*)d_in[1];
    const float* cls_b_in  = (const float*)d_in[2];
    const float* cls_w_hid = (const float*)d_in[3];
    const float* cls_b_hid = (const float*)d_in[4];
    const float* cls_w_out = (const float*)d_in[5];
    const float* cls_b_out = (const float*)d_in[6];
    const float* obj_w_in  = (const float*)d_in[7];
    const float* obj_b_in  = (const float*)d_in[8];
    const float* obj_w_hid = (const float*)d_in[9];
    const float* obj_b_hid = (const float*)d_in[10];
    const float* obj_w_out = (const float*)d_in[11];
    const float* obj_b_out = (const float*)d_in[12];
    const float* box_w_in  = (const float*)d_in[13];
    const float* box_b_in  = (const float*)d_in[14];
    const float* box_w_hid = (const float*)d_in[15];
    const float* box_b_hid = (const float*)d_in[16];
    const float* box_w_out = (const float*)d_in[17];
    const float* box_b_out = (const float*)d_in[18];
    float* out = (float*)d_out;

    const int persist_smem = 6 * STG * (int)sizeof(float);   // 101376 B
    cudaFuncSetAttribute(persist_k, cudaFuncAttributeMaxDynamicSharedMemorySize, persist_smem);
    cudaFuncSetAttribute(nms_reduce_k, cudaFuncAttributeMaxDynamicSharedMemorySize, 131072);

    int nsm = 148;
    cudaDeviceGetAttribute(&nsm, cudaDevAttrMultiProcessorCount, 0);
    int grid = 2 * nsm;
    if (grid > TOT_ALL) grid = TOT_ALL;

    // 0) reset per-replay state + transpose weights
    reset_k<<<1, 256>>>();
    wtrans_k<<<dim3(8, 8, 15), dim3(32, 8)>>>(cls_w_in, obj_w_in, box_w_in,
                                              cls_w_hid, obj_w_hid, box_w_hid);

    // 1) persistent GEMM chain (5 layers x 3 heads) + fused out-layers/decode
    persist_k<<<grid, 256, persist_smem>>>(feat,
                                           cls_b_in, obj_b_in, box_b_in,
                                           cls_b_hid, obj_b_hid, box_b_hid,
                                           cls_w_out, cls_b_out,
                                           obj_w_out, obj_b_out,
                                           box_w_out, box_b_out);

    // 2) exact per-batch top-1000
    topk_k<<<BB, 1024>>>();

    // 3) NMS
    nms_mask_k<<<dim3(NMS_CAND, BB), 1024>>>();
    nms_reduce_k<<<BB, 1024, NMS_CAND * 32 * (int)sizeof(unsigned)>>>();

    // 4) final top-100 select
    select_k<<<BB, 1024>>>(out);
}